// round 3
// baseline (speedup 1.0000x reference)
#include <cuda_runtime.h>
#include <cuda_bf16.h>
#include <cstdint>

// Problem dims
#define BB 4
#define SS 4096
#define HH 8
#define DD 64
#define HD 512                 // H*D
#define TOK (BB*SS)            // 16384 tokens
#define ROWS (TOK*HH)          // 131072 gemm rows
#define CC 32                  // chunk length along S
#define NC (SS/CC)             // 128 chunks per batch
#define BC (BB*NC)             // 512 scan blocks
#define N3D 192

// ---------------- scratch (device globals; no allocations allowed) ----------
__device__ float g_csum[ROWS*DD];     // normalized csum  [B,S,H,D]
__device__ float g_fg  [ROWS*DD];
__device__ float g_igh [ROWS*DD];
__device__ float g_cell[ROWS*DD];
__device__ float g_chunksum[BC*HD];
__device__ float g_chunkpre[BC*HD];
__device__ float g_A [BC*HD];
__device__ float g_Bv[BC*HD];
__device__ float g_carry[BC*HD];

// ---------------- K1: per-chunk sums of X ------------------------------------
__global__ void k1_chunksum(const float* __restrict__ x) {
    int bc = blockIdx.x;            // b*NC + c
    int b = bc / NC, c = bc % NC;
    int tid = threadIdx.x;          // 512 = (h,d)
    const float* p = x + ((size_t)(b*SS + c*CC))*HD + tid;
    float s = 0.f;
    #pragma unroll
    for (int i = 0; i < CC; i++) s += p[(size_t)i*HD];
    g_chunksum[(size_t)bc*HD + tid] = s;
}

// ---------------- K2: exclusive scan of chunk sums over c --------------------
__global__ void k2_scanchunks() {
    int b = blockIdx.x, tid = threadIdx.x;
    float carry = 0.f;
    for (int c = 0; c < NC; c++) {
        size_t idx = (size_t)(b*NC + c)*HD + tid;
        float t = g_chunksum[idx];
        g_chunkpre[idx] = carry;
        carry += t;
    }
}

// ---------------- K3: exclusive cumsum + LayerNorm over (H,D) ----------------
__global__ void k3_csum_ln(const float* __restrict__ x,
                           const float* __restrict__ gamma,
                           const float* __restrict__ beta) {
    int bc = blockIdx.x;
    int b = bc / NC, c = bc % NC;
    int tid = threadIdx.x;          // 512
    int warp = tid >> 5, lane = tid & 31;
    __shared__ float sm_s[16], sm_q[16], sm_mi[2];

    float run = g_chunkpre[(size_t)bc*HD + tid];
    float ga = gamma[tid], be = beta[tid];
    size_t base = ((size_t)(b*SS + c*CC))*HD + tid;
    const float* px = x + base;
    float* pc = g_csum + base;

    for (int i = 0; i < CC; i++) {
        float val = run;            // exclusive cumsum value at this token
        run += px[(size_t)i*HD];
        float s = val, q = val*val;
        #pragma unroll
        for (int o = 16; o; o >>= 1) {
            s += __shfl_xor_sync(0xffffffffu, s, o);
            q += __shfl_xor_sync(0xffffffffu, q, o);
        }
        if (lane == 0) { sm_s[warp] = s; sm_q[warp] = q; }
        __syncthreads();
        if (tid < 32) {
            float s2 = (lane < 16) ? sm_s[lane] : 0.f;
            float q2 = (lane < 16) ? sm_q[lane] : 0.f;
            #pragma unroll
            for (int o = 8; o; o >>= 1) {
                s2 += __shfl_xor_sync(0xffffffffu, s2, o);
                q2 += __shfl_xor_sync(0xffffffffu, q2, o);
            }
            if (lane == 0) {
                float m = s2 * (1.f/512.f);
                float v = q2 * (1.f/512.f) - m*m;
                sm_mi[0] = m;
                sm_mi[1] = rsqrtf(v + 1e-5f);
            }
        }
        __syncthreads();
        pc[(size_t)i*HD] = (val - sm_mi[0]) * sm_mi[1] * ga + be;
    }
}

// ---------------- K4: GEMM1 [X|csum] @ W_hid + gates -------------------------
// 64-row tile, 128 threads, thread tile 8 rows x 12 cols (cols tx+16j).
__global__ __launch_bounds__(128) void k4_gemm1(const float* __restrict__ x,
                                                const float* __restrict__ Wh,
                                                const float* __restrict__ bh) {
    __shared__ float As[16][64];        // [kk][row]
    __shared__ float Ws[16*N3D];        // [kk][col] linear
    int row0 = blockIdx.x * 64;
    int tid = threadIdx.x;
    int ty = tid >> 4;                  // 0..7 -> rows ty*8..+7
    int tx = tid & 15;                  // cols tx + 16*j
    float acc[8][12];
    #pragma unroll
    for (int r = 0; r < 8; r++)
        #pragma unroll
        for (int j = 0; j < 12; j++) acc[r][j] = 0.f;

    int ar = tid >> 1;                  // A-load row 0..63
    int akq = (tid & 1) * 8;            // A-load k offset 0/8

    #pragma unroll 1
    for (int kb = 0; kb < 8; kb++) {
        const float* asrc = (kb < 4)
            ? (x      + (size_t)row0*64 + kb*16)
            : (g_csum + (size_t)row0*64 + (kb-4)*16);
        {
            const float* p = asrc + (size_t)ar*64 + akq;
            float4 v0 = *(const float4*)p;
            float4 v1 = *(const float4*)(p + 4);
            As[akq+0][ar]=v0.x; As[akq+1][ar]=v0.y; As[akq+2][ar]=v0.z; As[akq+3][ar]=v0.w;
            As[akq+4][ar]=v1.x; As[akq+5][ar]=v1.y; As[akq+6][ar]=v1.z; As[akq+7][ar]=v1.w;
        }
        {
            const float* wsrc = Wh + kb*16*N3D;
            #pragma unroll
            for (int j = 0; j < 24; j++)
                Ws[j*128 + tid] = wsrc[j*128 + tid];
        }
        __syncthreads();
        #pragma unroll 4
        for (int kk = 0; kk < 16; kk++) {
            float a[8];
            float4 u0 = *(const float4*)&As[kk][ty*8];
            float4 u1 = *(const float4*)&As[kk][ty*8 + 4];
            a[0]=u0.x; a[1]=u0.y; a[2]=u0.z; a[3]=u0.w;
            a[4]=u1.x; a[5]=u1.y; a[6]=u1.z; a[7]=u1.w;
            float w[12];
            #pragma unroll
            for (int j = 0; j < 12; j++) w[j] = Ws[kk*N3D + tx + 16*j];
            #pragma unroll
            for (int r = 0; r < 8; r++)
                #pragma unroll
                for (int j = 0; j < 12; j++)
                    acc[r][j] = fmaf(a[r], w[j], acc[r][j]);
        }
        __syncthreads();
    }

    // epilogue: j<4 -> igate(d), j+4 -> fgate(d+64), j+8 -> hidden(d+128)
    #pragma unroll
    for (int j = 0; j < 4; j++) {
        int d = tx + 16*j;
        float bi = bh[d], bf = bh[64 + d], bhd = bh[128 + d];
        #pragma unroll
        for (int r = 0; r < 8; r++) {
            int row = row0 + ty*8 + r;
            float ig  = acc[r][j]     + bi;
            float fgv = acc[r][j + 4] + bf;
            float hid = acc[r][j + 8] + bhd;
            float fg  = 1.f / (1.f + __expf(-fgv));
            float sg  = 1.f / (1.f + __expf(-ig));
            float igh = sg * fmaxf(hid, 0.f);
            g_fg [(size_t)row*64 + d] = fg;
            g_igh[(size_t)row*64 + d] = igh;
        }
    }
}

// ---------------- K5: per-chunk cell-scan states (A = prod f, Bv = zero-init scan)
__global__ void k5_chunkscan() {
    int bc = blockIdx.x;
    int b = bc / NC, c = bc % NC;
    int tid = threadIdx.x;
    size_t base = ((size_t)(b*SS + c*CC))*HD + tid;
    const float* pf = g_fg + base;
    const float* pg = g_igh + base;
    float a = 1.f, bv = 0.f;
    #pragma unroll
    for (int i = 0; i < CC; i++) {
        float f = pf[(size_t)i*HD], g = pg[(size_t)i*HD];
        a *= f;
        bv = bv * f + g;
    }
    g_A [(size_t)bc*HD + tid] = a;
    g_Bv[(size_t)bc*HD + tid] = bv;
}

// ---------------- K6: serial combine of chunk states -------------------------
__global__ void k6_combine(const float* __restrict__ initcx) {
    int b = blockIdx.x, tid = threadIdx.x;
    float carry = initcx[tid];
    for (int c = 0; c < NC; c++) {
        size_t idx = (size_t)(b*NC + c)*HD + tid;
        g_carry[idx] = carry;
        carry = g_A[idx] * carry + g_Bv[idx];
    }
}

// ---------------- K7a: replay cell within chunks ------------------------------
__global__ void k7a_cell() {
    int bc = blockIdx.x;
    int b = bc / NC, c = bc % NC;
    int tid = threadIdx.x;
    float cell = g_carry[(size_t)bc*HD + tid];
    size_t base = ((size_t)(b*SS + c*CC))*HD + tid;
    const float* pf = g_fg + base;
    const float* pg = g_igh + base;
    float* pc = g_cell + base;
    #pragma unroll
    for (int i = 0; i < CC; i++) {
        cell = pf[(size_t)i*HD] * cell + pg[(size_t)i*HD];
        pc[(size_t)i*HD] = cell;
    }
}

// ---------------- K7b: GEMM2 [X|cell] @ W_og, out = sigmoid(.)*cell ----------
__global__ __launch_bounds__(128) void k7b_gemm2(const float* __restrict__ x,
                                                 const float* __restrict__ Wog,
                                                 const float* __restrict__ bog,
                                                 float* __restrict__ out) {
    __shared__ float As[16][64];
    __shared__ float Ws[16*64];
    int row0 = blockIdx.x * 64;
    int tid = threadIdx.x;
    int ty = tid >> 4;                  // rows ty*8..+7
    int tx = tid & 15;                  // cols tx + 16*j, j<4
    float acc[8][4];
    #pragma unroll
    for (int r = 0; r < 8; r++)
        #pragma unroll
        for (int j = 0; j < 4; j++) acc[r][j] = 0.f;

    int ar = tid >> 1;
    int akq = (tid & 1) * 8;

    #pragma unroll 1
    for (int kb = 0; kb < 8; kb++) {
        const float* asrc = (kb < 4)
            ? (x      + (size_t)row0*64 + kb*16)
            : (g_cell + (size_t)row0*64 + (kb-4)*16);
        {
            const float* p = asrc + (size_t)ar*64 + akq;
            float4 v0 = *(const float4*)p;
            float4 v1 = *(const float4*)(p + 4);
            As[akq+0][ar]=v0.x; As[akq+1][ar]=v0.y; As[akq+2][ar]=v0.z; As[akq+3][ar]=v0.w;
            As[akq+4][ar]=v1.x; As[akq+5][ar]=v1.y; As[akq+6][ar]=v1.z; As[akq+7][ar]=v1.w;
        }
        {
            const float* wsrc = Wog + kb*16*64;
            #pragma unroll
            for (int j = 0; j < 8; j++)
                Ws[j*128 + tid] = wsrc[j*128 + tid];
        }
        __syncthreads();
        #pragma unroll 8
        for (int kk = 0; kk < 16; kk++) {
            float a[8];
            float4 u0 = *(const float4*)&As[kk][ty*8];
            float4 u1 = *(const float4*)&As[kk][ty*8 + 4];
            a[0]=u0.x; a[1]=u0.y; a[2]=u0.z; a[3]=u0.w;
            a[4]=u1.x; a[5]=u1.y; a[6]=u1.z; a[7]=u1.w;
            float w[4];
            #pragma unroll
            for (int j = 0; j < 4; j++) w[j] = Ws[kk*64 + tx + 16*j];
            #pragma unroll
            for (int r = 0; r < 8; r++)
                #pragma unroll
                for (int j = 0; j < 4; j++)
                    acc[r][j] = fmaf(a[r], w[j], acc[r][j]);
        }
        __syncthreads();
    }

    #pragma unroll
    for (int j = 0; j < 4; j++) {
        int cidx = tx + 16*j;
        float bo = bog[cidx];
        #pragma unroll
        for (int r = 0; r < 8; r++) {
            int row = row0 + ty*8 + r;
            float cell = g_cell[(size_t)row*64 + cidx];
            float og = 1.f / (1.f + __expf(-(acc[r][j] + bo)));
            out[(size_t)row*64 + cidx] = og * cell;
        }
    }
}

// ---------------- launch ------------------------------------------------------
extern "C" void kernel_launch(void* const* d_in, const int* in_sizes, int n_in,
                              void* d_out, int out_size) {
    const float* x      = (const float*)d_in[0];   // [B,S,H,D]
    const float* Wh     = (const float*)d_in[1];   // [128,192]
    const float* bh     = (const float*)d_in[2];   // [192]
    const float* Wog    = (const float*)d_in[3];   // [128,64]
    const float* bog    = (const float*)d_in[4];   // [64]
    const float* gamma  = (const float*)d_in[5];   // [512]
    const float* beta   = (const float*)d_in[6];   // [512]
    const float* initcx = (const float*)d_in[7];   // [512]
    float* out = (float*)d_out;

    k1_chunksum<<<BC, 512>>>(x);
    k2_scanchunks<<<BB, 512>>>();
    k3_csum_ln<<<BC, 512>>>(x, gamma, beta);
    k4_gemm1<<<ROWS/64, 128>>>(x, Wh, bh);
    k5_chunkscan<<<BC, 512>>>();
    k6_combine<<<BB, 512>>>(initcx);
    k7a_cell<<<BC, 512>>>();
    k7b_gemm2<<<ROWS/64, 128>>>(x, Wog, bog, out);
}

// round 5
// speedup vs baseline: 1.3673x; 1.3673x over previous
#include <cuda_runtime.h>
#include <cuda_bf16.h>
#include <cstdint>

// Problem dims
#define BB 4
#define SS 4096
#define HH 8
#define DD 64
#define HD 512
#define TOK (BB*SS)
#define ROWS (TOK*HH)          // 131072 gemm rows
#define CC 32
#define NC (SS/CC)
#define BC (BB*NC)

// ================= scratch ====================================================
__device__ float g_csum[ROWS*DD];
__device__ float g_fg  [ROWS*DD];
__device__ float g_igh [ROWS*DD];
__device__ float g_cell[ROWS*DD];
__device__ float g_chunksum[BC*HD];
__device__ float g_chunkpre[BC*HD];
__device__ float g_A [BC*HD];
__device__ float g_Bv[BC*HD];
__device__ float g_carry[BC*HD];
// W pre-packed in mma B-fragment order: [ks][nt][lane][2] u32 (bf16x2 each)
__device__ uint32_t g_WhF_hi[12288];   // GEMM1: 8 ks * 24 nt * 32 * 2
__device__ uint32_t g_WhF_lo[12288];
__device__ uint32_t g_WoF_hi[4096];    // GEMM2: 8 ks * 8 nt * 32 * 2
__device__ uint32_t g_WoF_lo[4096];

// ================= helpers ====================================================
__device__ __forceinline__ float sigmoidf_(float v) { return 1.f / (1.f + __expf(-v)); }

__device__ __forceinline__ void split_bf16(float v, unsigned short& hi, unsigned short& lo) {
    __nv_bfloat16 h = __float2bfloat16(v);
    __nv_bfloat16 l = __float2bfloat16(v - __bfloat162float(h));
    hi = __bfloat16_as_ushort(h);
    lo = __bfloat16_as_ushort(l);
}

#define MMA4(c, a0,a1,a2,a3, b0,b1) \
    asm volatile("mma.sync.aligned.m16n8k16.row.col.f32.bf16.bf16.f32 " \
        "{%0,%1,%2,%3}, {%4,%5,%6,%7}, {%8,%9}, {%0,%1,%2,%3};" \
        : "+f"((c)[0]),"+f"((c)[1]),"+f"((c)[2]),"+f"((c)[3]) \
        : "r"(a0),"r"(a1),"r"(a2),"r"(a3),"r"(b0),"r"(b1))

// ================= prep: W -> B-fragment images ===============================
// GEMM1 column permutation: logical col' = nt*8 + u (nt 0..23, u 0..7)
//   nhalf = nt/12, ntl = nt%12, gate = ntl/4, d = nhalf*32 + (ntl%4)*8 + u
//   original W col = gate*64 + d.
// This puts the (i,f,h) triple for a given d into c[dt], c[dt+4], c[dt+8] of the
// same thread in the GEMM epilogue.
__global__ void kprep_w(const float* __restrict__ Wh, const float* __restrict__ Wog) {
    int t = blockIdx.x * blockDim.x + threadIdx.x;
    int stride = gridDim.x * blockDim.x;
    for (int idx = t; idx < 12288; idx += stride) {
        int reg  = idx & 1;
        int lane = (idx >> 1) & 31;
        int nt   = (idx >> 6) % 24;
        int ks   = (idx >> 6) / 24;
        int nhalf = nt / 12, ntl = nt % 12;
        int gate = ntl / 4;
        int d = nhalf*32 + (ntl % 4)*8 + (lane >> 2);
        int n = gate*64 + d;
        int k0 = ks*16 + (lane & 3)*2 + reg*8;
        unsigned short h0, l0, h1, l1;
        split_bf16(Wh[(size_t)k0*192 + n], h0, l0);
        split_bf16(Wh[(size_t)(k0+1)*192 + n], h1, l1);
        g_WhF_hi[idx] = (uint32_t)h0 | ((uint32_t)h1 << 16);
        g_WhF_lo[idx] = (uint32_t)l0 | ((uint32_t)l1 << 16);
    }
    for (int idx = t; idx < 4096; idx += stride) {
        int reg  = idx & 1;
        int lane = (idx >> 1) & 31;
        int nt   = (idx >> 6) % 8;
        int ks   = (idx >> 6) / 8;
        int n = nt*8 + (lane >> 2);
        int k0 = ks*16 + (lane & 3)*2 + reg*8;
        unsigned short h0, l0, h1, l1;
        split_bf16(Wog[(size_t)k0*64 + n], h0, l0);
        split_bf16(Wog[(size_t)(k0+1)*64 + n], h1, l1);
        g_WoF_hi[idx] = (uint32_t)h0 | ((uint32_t)h1 << 16);
        g_WoF_lo[idx] = (uint32_t)l0 | ((uint32_t)l1 << 16);
    }
}

// ================= scans (unchanged from R3, known-good) ======================
__global__ void k1_chunksum(const float* __restrict__ x) {
    int bc = blockIdx.x;
    int b = bc / NC, c = bc % NC;
    int tid = threadIdx.x;
    const float* p = x + ((size_t)(b*SS + c*CC))*HD + tid;
    float s = 0.f;
    #pragma unroll
    for (int i = 0; i < CC; i++) s += p[(size_t)i*HD];
    g_chunksum[(size_t)bc*HD + tid] = s;
}

__global__ void k2_scanchunks() {
    int b = blockIdx.x, tid = threadIdx.x;
    float carry = 0.f;
    for (int c = 0; c < NC; c++) {
        size_t idx = (size_t)(b*NC + c)*HD + tid;
        float t = g_chunksum[idx];
        g_chunkpre[idx] = carry;
        carry += t;
    }
}

__global__ void k3_csum_ln(const float* __restrict__ x,
                           const float* __restrict__ gamma,
                           const float* __restrict__ beta) {
    int bc = blockIdx.x;
    int b = bc / NC, c = bc % NC;
    int tid = threadIdx.x;
    int warp = tid >> 5, lane = tid & 31;
    __shared__ float sm_s[16], sm_q[16], sm_mi[2];

    float run = g_chunkpre[(size_t)bc*HD + tid];
    float ga = gamma[tid], be = beta[tid];
    size_t base = ((size_t)(b*SS + c*CC))*HD + tid;
    const float* px = x + base;
    float* pc = g_csum + base;

    for (int i = 0; i < CC; i++) {
        float val = run;
        run += px[(size_t)i*HD];
        float s = val, q = val*val;
        #pragma unroll
        for (int o = 16; o; o >>= 1) {
            s += __shfl_xor_sync(0xffffffffu, s, o);
            q += __shfl_xor_sync(0xffffffffu, q, o);
        }
        if (lane == 0) { sm_s[warp] = s; sm_q[warp] = q; }
        __syncthreads();
        if (tid < 32) {
            float s2 = (lane < 16) ? sm_s[lane] : 0.f;
            float q2 = (lane < 16) ? sm_q[lane] : 0.f;
            #pragma unroll
            for (int o = 8; o; o >>= 1) {
                s2 += __shfl_xor_sync(0xffffffffu, s2, o);
                q2 += __shfl_xor_sync(0xffffffffu, q2, o);
            }
            if (lane == 0) {
                float m = s2 * (1.f/512.f);
                float v = q2 * (1.f/512.f) - m*m;
                sm_mi[0] = m;
                sm_mi[1] = rsqrtf(v + 1e-5f);
            }
        }
        __syncthreads();
        pc[(size_t)i*HD] = (val - sm_mi[0]) * sm_mi[1] * ga + be;
    }
}

__global__ void k5_chunkscan() {
    int bc = blockIdx.x;
    int b = bc / NC, c = bc % NC;
    int tid = threadIdx.x;
    size_t base = ((size_t)(b*SS + c*CC))*HD + tid;
    const float* pf = g_fg + base;
    const float* pg = g_igh + base;
    float a = 1.f, bv = 0.f;
    #pragma unroll
    for (int i = 0; i < CC; i++) {
        float f = pf[(size_t)i*HD], g = pg[(size_t)i*HD];
        a *= f;
        bv = bv * f + g;
    }
    g_A [(size_t)bc*HD + tid] = a;
    g_Bv[(size_t)bc*HD + tid] = bv;
}

__global__ void k6_combine(const float* __restrict__ initcx) {
    int b = blockIdx.x, tid = threadIdx.x;
    float carry = initcx[tid];
    for (int c = 0; c < NC; c++) {
        size_t idx = (size_t)(b*NC + c)*HD + tid;
        g_carry[idx] = carry;
        carry = g_A[idx] * carry + g_Bv[idx];
    }
}

__global__ void k7a_cell() {
    int bc = blockIdx.x;
    int b = bc / NC, c = bc % NC;
    int tid = threadIdx.x;
    float cell = g_carry[(size_t)bc*HD + tid];
    size_t base = ((size_t)(b*SS + c*CC))*HD + tid;
    const float* pf = g_fg + base;
    const float* pg = g_igh + base;
    float* pc = g_cell + base;
    #pragma unroll
    for (int i = 0; i < CC; i++) {
        cell = pf[(size_t)i*HD] * cell + pg[(size_t)i*HD];
        pc[(size_t)i*HD] = cell;
    }
}

// ================= A tile convert: f32 -> bf16 hi/lo in SMEM ==================
// SMEM layout: Ahi[128][136] ushort, Alo[128][136] ushort (pitch 136 -> no LDS
// conflicts on fragment reads). A = [x(k<64) | other(k>=64)].
#define APITCH 136
#define A_SMEM_BYTES (2*128*APITCH*2)   // 69632

__device__ __forceinline__ void convert_A(unsigned short* Ahi, unsigned short* Alo,
                                          const float* __restrict__ x,
                                          const float* __restrict__ other,
                                          int row0, int tid, int nthreads) {
    for (int r = tid >> 2; r < 128; r += (nthreads >> 2)) {
        int q = tid & 3;                 // k quarter (32 k each)
        const float* src = (q < 2)
            ? (x     + (size_t)(row0 + r)*64 + q*32)
            : (g_csum + 0, other + (size_t)(row0 + r)*64 + (q-2)*32);
        int kbase = q*32;
        const float4* p4 = (const float4*)src;
        #pragma unroll
        for (int i = 0; i < 8; i++) {
            float4 v = p4[i];
            unsigned short h0,l0,h1,l1,h2,l2,h3,l3;
            split_bf16(v.x, h0, l0);
            split_bf16(v.y, h1, l1);
            split_bf16(v.z, h2, l2);
            split_bf16(v.w, h3, l3);
            int k = kbase + i*4;
            *(uint32_t*)&Ahi[r*APITCH + k]     = (uint32_t)h0 | ((uint32_t)h1 << 16);
            *(uint32_t*)&Ahi[r*APITCH + k + 2] = (uint32_t)h2 | ((uint32_t)h3 << 16);
            *(uint32_t*)&Alo[r*APITCH + k]     = (uint32_t)l0 | ((uint32_t)l1 << 16);
            *(uint32_t*)&Alo[r*APITCH + k + 2] = (uint32_t)l2 | ((uint32_t)l3 << 16);
        }
    }
}

// ================= K4: GEMM1 via mma.sync + fused gates =======================
// Block: 512 thr (16 warps). Warp: rows slab*16..+16, cols nhalf*96..+96.
__global__ __launch_bounds__(512) void k4_mma(const float* __restrict__ x,
                                              const float* __restrict__ bhid) {
    extern __shared__ unsigned short smu[];
    unsigned short* Ahi = smu;
    unsigned short* Alo = smu + 128*APITCH;
    int tid = threadIdx.x, lane = tid & 31, wid = tid >> 5;
    int row0 = blockIdx.x * 128;

    convert_A(Ahi, Alo, x, g_csum, row0, tid, 512);
    __syncthreads();

    int slab = wid >> 1, nhalf = wid & 1;
    int m0 = slab*16 + (lane >> 2);
    int kq = (lane & 3)*2;

    float c[12][4];
    #pragma unroll
    for (int j = 0; j < 12; j++)
        #pragma unroll
        for (int e = 0; e < 4; e++) c[j][e] = 0.f;

    #pragma unroll
    for (int ks = 0; ks < 8; ks++) {
        int ka = ks*16 + kq;
        uint32_t ah0 = *(const uint32_t*)&Ahi[m0*APITCH + ka];
        uint32_t ah1 = *(const uint32_t*)&Ahi[(m0+8)*APITCH + ka];
        uint32_t ah2 = *(const uint32_t*)&Ahi[m0*APITCH + ka + 8];
        uint32_t ah3 = *(const uint32_t*)&Ahi[(m0+8)*APITCH + ka + 8];
        uint32_t al0 = *(const uint32_t*)&Alo[m0*APITCH + ka];
        uint32_t al1 = *(const uint32_t*)&Alo[(m0+8)*APITCH + ka];
        uint32_t al2 = *(const uint32_t*)&Alo[m0*APITCH + ka + 8];
        uint32_t al3 = *(const uint32_t*)&Alo[(m0+8)*APITCH + ka + 8];
        const uint32_t* bbh = g_WhF_hi + ((size_t)(ks*24 + nhalf*12)*32 + lane)*2;
        const uint32_t* bbl = g_WhF_lo + ((size_t)(ks*24 + nhalf*12)*32 + lane)*2;
        #pragma unroll
        for (int nt = 0; nt < 12; nt++) {
            uint2 bh2 = *(const uint2*)(bbh + nt*64);
            uint2 bl2 = *(const uint2*)(bbl + nt*64);
            MMA4(c[nt], ah0, ah1, ah2, ah3, bh2.x, bh2.y);
            MMA4(c[nt], ah0, ah1, ah2, ah3, bl2.x, bl2.y);
            MMA4(c[nt], al0, al1, al2, al3, bh2.x, bh2.y);
        }
    }

    // epilogue: gate triple for d lives in c[dt], c[dt+4], c[dt+8]
    int u0 = (lane & 3)*2;
    int rbase = row0 + slab*16 + (lane >> 2);
    #pragma unroll
    for (int dt = 0; dt < 4; dt++) {
        int d = nhalf*32 + dt*8 + u0;
        float bi0 = bhid[d],       bi1 = bhid[d+1];
        float bf0 = bhid[64 + d],  bf1 = bhid[64 + d + 1];
        float bq0 = bhid[128 + d], bq1 = bhid[128 + d + 1];
        #pragma unroll
        for (int h = 0; h < 2; h++) {
            int row = rbase + h*8;
            float i0 = c[dt][h*2]   + bi0, i1 = c[dt][h*2+1]   + bi1;
            float f0 = c[dt+4][h*2] + bf0, f1 = c[dt+4][h*2+1] + bf1;
            float q0 = c[dt+8][h*2] + bq0, q1 = c[dt+8][h*2+1] + bq1;
            float2 vf, vi;
            vf.x = sigmoidf_(f0);
            vf.y = sigmoidf_(f1);
            vi.x = sigmoidf_(i0) * fmaxf(q0, 0.f);
            vi.y = sigmoidf_(i1) * fmaxf(q1, 0.f);
            *(float2*)&g_fg [(size_t)row*64 + d] = vf;
            *(float2*)&g_igh[(size_t)row*64 + d] = vi;
        }
    }
}

// ================= K7b: GEMM2 via mma.sync + fused output gate ================
// Block: 256 thr (8 warps). Warp: rows wid*16..+16, all 64 cols.
__global__ __launch_bounds__(256) void k7b_mma(const float* __restrict__ x,
                                               const float* __restrict__ bog,
                                               float* __restrict__ out) {
    extern __shared__ unsigned short smu[];
    unsigned short* Ahi = smu;
    unsigned short* Alo = smu + 128*APITCH;
    int tid = threadIdx.x, lane = tid & 31, wid = tid >> 5;
    int row0 = blockIdx.x * 128;

    convert_A(Ahi, Alo, x, g_cell, row0, tid, 256);
    __syncthreads();

    int m0 = wid*16 + (lane >> 2);
    int kq = (lane & 3)*2;

    float c[8][4];
    #pragma unroll
    for (int j = 0; j < 8; j++)
        #pragma unroll
        for (int e = 0; e < 4; e++) c[j][e] = 0.f;

    #pragma unroll
    for (int ks = 0; ks < 8; ks++) {
        int ka = ks*16 + kq;
        uint32_t ah0 = *(const uint32_t*)&Ahi[m0*APITCH + ka];
        uint32_t ah1 = *(const uint32_t*)&Ahi[(m0+8)*APITCH + ka];
        uint32_t ah2 = *(const uint32_t*)&Ahi[m0*APITCH + ka + 8];
        uint32_t ah3 = *(const uint32_t*)&Ahi[(m0+8)*APITCH + ka + 8];
        uint32_t al0 = *(const uint32_t*)&Alo[m0*APITCH + ka];
        uint32_t al1 = *(const uint32_t*)&Alo[(m0+8)*APITCH + ka];
        uint32_t al2 = *(const uint32_t*)&Alo[m0*APITCH + ka + 8];
        uint32_t al3 = *(const uint32_t*)&Alo[(m0+8)*APITCH + ka + 8];
        const uint32_t* bbh = g_WoF_hi + ((size_t)(ks*8)*32 + lane)*2;
        const uint32_t* bbl = g_WoF_lo + ((size_t)(ks*8)*32 + lane)*2;
        #pragma unroll
        for (int nt = 0; nt < 8; nt++) {
            uint2 bh2 = *(const uint2*)(bbh + nt*64);
            uint2 bl2 = *(const uint2*)(bbl + nt*64);
            MMA4(c[nt], ah0, ah1, ah2, ah3, bh2.x, bh2.y);
            MMA4(c[nt], ah0, ah1, ah2, ah3, bl2.x, bl2.y);
            MMA4(c[nt], al0, al1, al2, al3, bh2.x, bh2.y);
        }
    }

    int u0 = (lane & 3)*2;
    int rbase = row0 + wid*16 + (lane >> 2);
    #pragma unroll
    for (int nt = 0; nt < 8; nt++) {
        int d = nt*8 + u0;
        float b0 = bog[d], b1 = bog[d+1];
        #pragma unroll
        for (int h = 0; h < 2; h++) {
            int row = rbase + h*8;
            float2 cv = *(const float2*)&g_cell[(size_t)row*64 + d];
            float2 ov;
            ov.x = sigmoidf_(c[nt][h*2]   + b0) * cv.x;
            ov.y = sigmoidf_(c[nt][h*2+1] + b1) * cv.y;
            *(float2*)&out[(size_t)row*64 + d] = ov;
        }
    }
}

// ================= launch =====================================================
extern "C" void kernel_launch(void* const* d_in, const int* in_sizes, int n_in,
                              void* d_out, int out_size) {
    const float* x      = (const float*)d_in[0];
    const float* Wh     = (const float*)d_in[1];
    const float* bh     = (const float*)d_in[2];
    const float* Wog    = (const float*)d_in[3];
    const float* bog    = (const float*)d_in[4];
    const float* gamma  = (const float*)d_in[5];
    const float* beta   = (const float*)d_in[6];
    const float* initcx = (const float*)d_in[7];
    float* out = (float*)d_out;

    static bool attr_done = false;
    if (!attr_done) {
        cudaFuncSetAttribute(k4_mma,  cudaFuncAttributeMaxDynamicSharedMemorySize, A_SMEM_BYTES);
        cudaFuncSetAttribute(k7b_mma, cudaFuncAttributeMaxDynamicSharedMemorySize, A_SMEM_BYTES);
        attr_done = true;
    }

    kprep_w<<<48, 256>>>(Wh, Wog);
    k1_chunksum<<<BC, 512>>>(x);
    k2_scanchunks<<<BB, 512>>>();
    k3_csum_ln<<<BC, 512>>>(x, gamma, beta);
    k4_mma<<<ROWS/128, 512, A_SMEM_BYTES>>>(x, bh);
    k5_chunkscan<<<BC, 512>>>();
    k6_combine<<<BB, 512>>>(initcx);
    k7a_cell<<<BC, 512>>>();
    k7b_mma<<<ROWS/128, 256, A_SMEM_BYTES>>>(x, bog, out);
}

// round 6
// speedup vs baseline: 1.6203x; 1.1851x over previous
#include <cuda_runtime.h>
#include <cuda_bf16.h>
#include <cstdint>

// Problem dims
#define BB 4
#define SS 4096
#define HH 8
#define DD 64
#define HD 512
#define TOK (BB*SS)
#define ROWS (TOK*HH)          // 131072 gemm rows
#define CC 32
#define NC (SS/CC)
#define BC (BB*NC)

// ================= scratch ====================================================
__device__ float g_csum[ROWS*DD];
__device__ float g_fg  [ROWS*DD];
__device__ float g_igh [ROWS*DD];
__device__ float g_cell[ROWS*DD];
__device__ float g_chunksum[BC*HD];
__device__ float g_A [BC*HD];
__device__ float g_Bv[BC*HD];
// W pre-packed in mma B-fragment order: [ks][nt][lane][2] u32 (bf16x2 each)
__device__ uint32_t g_WhF_hi[12288];   // GEMM1: 8 ks * 24 nt * 32 * 2
__device__ uint32_t g_WhF_lo[12288];
__device__ uint32_t g_WoF_hi[4096];    // GEMM2: 8 ks * 8 nt * 32 * 2
__device__ uint32_t g_WoF_lo[4096];

// ================= helpers ====================================================
__device__ __forceinline__ float sigmoidf_(float v) { return 1.f / (1.f + __expf(-v)); }

__device__ __forceinline__ void split_bf16(float v, unsigned short& hi, unsigned short& lo) {
    __nv_bfloat16 h = __float2bfloat16(v);
    __nv_bfloat16 l = __float2bfloat16(v - __bfloat162float(h));
    hi = __bfloat16_as_ushort(h);
    lo = __bfloat16_as_ushort(l);
}

#define MMA4(c, a0,a1,a2,a3, b0,b1) \
    asm volatile("mma.sync.aligned.m16n8k16.row.col.f32.bf16.bf16.f32 " \
        "{%0,%1,%2,%3}, {%4,%5,%6,%7}, {%8,%9}, {%0,%1,%2,%3};" \
        : "+f"((c)[0]),"+f"((c)[1]),"+f"((c)[2]),"+f"((c)[3]) \
        : "r"(a0),"r"(a1),"r"(a2),"r"(a3),"r"(b0),"r"(b1))

// ================= prep: W -> B-fragment images ===============================
__global__ void kprep_w(const float* __restrict__ Wh, const float* __restrict__ Wog) {
    int t = blockIdx.x * blockDim.x + threadIdx.x;
    int stride = gridDim.x * blockDim.x;
    for (int idx = t; idx < 12288; idx += stride) {
        int reg  = idx & 1;
        int lane = (idx >> 1) & 31;
        int nt   = (idx >> 6) % 24;
        int ks   = (idx >> 6) / 24;
        int nhalf = nt / 12, ntl = nt % 12;
        int gate = ntl / 4;
        int d = nhalf*32 + (ntl % 4)*8 + (lane >> 2);
        int n = gate*64 + d;
        int k0 = ks*16 + (lane & 3)*2 + reg*8;
        unsigned short h0, l0, h1, l1;
        split_bf16(Wh[(size_t)k0*192 + n], h0, l0);
        split_bf16(Wh[(size_t)(k0+1)*192 + n], h1, l1);
        g_WhF_hi[idx] = (uint32_t)h0 | ((uint32_t)h1 << 16);
        g_WhF_lo[idx] = (uint32_t)l0 | ((uint32_t)l1 << 16);
    }
    for (int idx = t; idx < 4096; idx += stride) {
        int reg  = idx & 1;
        int lane = (idx >> 1) & 31;
        int nt   = (idx >> 6) % 8;
        int ks   = (idx >> 6) / 8;
        int n = nt*8 + (lane >> 2);
        int k0 = ks*16 + (lane & 3)*2 + reg*8;
        unsigned short h0, l0, h1, l1;
        split_bf16(Wog[(size_t)k0*64 + n], h0, l0);
        split_bf16(Wog[(size_t)(k0+1)*64 + n], h1, l1);
        g_WoF_hi[idx] = (uint32_t)h0 | ((uint32_t)h1 << 16);
        g_WoF_lo[idx] = (uint32_t)l0 | ((uint32_t)l1 << 16);
    }
}

// ================= K1: per-chunk sums of X ------------------------------------
__global__ void k1_chunksum(const float* __restrict__ x) {
    int bc = blockIdx.x;
    int b = bc / NC, c = bc % NC;
    int tid = threadIdx.x;
    const float* p = x + ((size_t)(b*SS + c*CC))*HD + tid;
    float s = 0.f;
    #pragma unroll
    for (int i = 0; i < CC; i++) s += p[(size_t)i*HD];
    g_chunksum[(size_t)bc*HD + tid] = s;
}

// ================= K3: prefix lookback + cumsum + LayerNorm ==================
// 3-phase, 2 barriers total. Prefix computed directly from L2-resident chunksums.
__global__ __launch_bounds__(512) void k3_csum_ln(const float* __restrict__ x,
                                                  const float* __restrict__ gamma,
                                                  const float* __restrict__ beta) {
    int bc = blockIdx.x;
    int b = bc / NC, c = bc % NC;
    int tid = threadIdx.x;
    int warp = tid >> 5, lane = tid & 31;
    __shared__ float sm_s[16][33];
    __shared__ float sm_q[16][33];
    __shared__ float sm_mean[32], sm_inv[32];

    // prefix: sum of predecessor chunk sums (independent loads, L2 resident)
    float run = 0.f;
    {
        const float* pcs = g_chunksum + (size_t)b*NC*HD + tid;
        int j = 0;
        for (; j + 4 <= c; j += 4)
            run += pcs[(size_t)(j+0)*HD] + pcs[(size_t)(j+1)*HD]
                 + pcs[(size_t)(j+2)*HD] + pcs[(size_t)(j+3)*HD];
        for (; j < c; j++) run += pcs[(size_t)j*HD];
    }

    float ga = gamma[tid], be = beta[tid];
    size_t base = ((size_t)(b*SS + c*CC))*HD + tid;
    const float* px = x + base;
    float* pc = g_csum + base;

    // phase 1: per-token per-warp partial (sum, sumsq)
    float r1 = run;
    #pragma unroll
    for (int i = 0; i < CC; i++) {
        float val = r1;
        r1 += px[(size_t)i*HD];
        float s = val, q = val*val;
        #pragma unroll
        for (int o = 16; o; o >>= 1) {
            s += __shfl_xor_sync(0xffffffffu, s, o);
            q += __shfl_xor_sync(0xffffffffu, q, o);
        }
        if (lane == 0) { sm_s[warp][i] = s; sm_q[warp][i] = q; }
    }
    __syncthreads();

    // phase 2: reduce 16 warp-partials per token (16-thread groups in-warp)
    {
        int t = tid >> 4, k = tid & 15;
        float s = sm_s[k][t], q = sm_q[k][t];
        #pragma unroll
        for (int o = 8; o; o >>= 1) {
            s += __shfl_xor_sync(0xffffffffu, s, o);
            q += __shfl_xor_sync(0xffffffffu, q, o);
        }
        if (k == 0) {
            float m = s * (1.f/512.f);
            float v = q * (1.f/512.f) - m*m;
            sm_mean[t] = m;
            sm_inv[t]  = rsqrtf(v + 1e-5f);
        }
    }
    __syncthreads();

    // phase 3: rewalk (x reloads hit L1) and write normalized
    float r2 = run;
    #pragma unroll
    for (int i = 0; i < CC; i++) {
        float val = r2;
        r2 += px[(size_t)i*HD];
        pc[(size_t)i*HD] = (val - sm_mean[i]) * sm_inv[i] * ga + be;
    }
}

// ================= K5: per-chunk cell-scan states =============================
__global__ void k5_chunkscan() {
    int bc = blockIdx.x;
    int b = bc / NC, c = bc % NC;
    int tid = threadIdx.x;
    size_t base = ((size_t)(b*SS + c*CC))*HD + tid;
    const float* pf = g_fg + base;
    const float* pg = g_igh + base;
    float a = 1.f, bv = 0.f;
    #pragma unroll
    for (int i = 0; i < CC; i++) {
        float f = pf[(size_t)i*HD], g = pg[(size_t)i*HD];
        a *= f;
        bv = bv * f + g;
    }
    g_A [(size_t)bc*HD + tid] = a;
    g_Bv[(size_t)bc*HD + tid] = bv;
}

// ================= K7a: lookback carry + replay cell ==========================
__global__ void k7a_cell(const float* __restrict__ initcx) {
    int bc = blockIdx.x;
    int b = bc / NC, c = bc % NC;
    int tid = threadIdx.x;

    float carry = initcx[tid];
    {
        const float* pA = g_A  + (size_t)b*NC*HD + tid;
        const float* pB = g_Bv + (size_t)b*NC*HD + tid;
        #pragma unroll 4
        for (int j = 0; j < c; j++)
            carry = pA[(size_t)j*HD] * carry + pB[(size_t)j*HD];
    }

    size_t base = ((size_t)(b*SS + c*CC))*HD + tid;
    const float* pf = g_fg + base;
    const float* pg = g_igh + base;
    float* pc = g_cell + base;
    float cell = carry;
    #pragma unroll
    for (int i = 0; i < CC; i++) {
        cell = pf[(size_t)i*HD] * cell + pg[(size_t)i*HD];
        pc[(size_t)i*HD] = cell;
    }
}

// ================= A tile convert: f32 -> bf16 hi/lo in SMEM ==================
#define APITCH 136
#define A_SMEM_BYTES (2*128*APITCH*2)   // 69632

__device__ __forceinline__ void convert_A(unsigned short* Ahi, unsigned short* Alo,
                                          const float* __restrict__ x,
                                          const float* __restrict__ other,
                                          int row0, int tid, int nthreads) {
    for (int r = tid >> 2; r < 128; r += (nthreads >> 2)) {
        int q = tid & 3;
        const float* src = (q < 2)
            ? (x     + (size_t)(row0 + r)*64 + q*32)
            : (other + (size_t)(row0 + r)*64 + (q-2)*32);
        int kbase = q*32;
        const float4* p4 = (const float4*)src;
        #pragma unroll
        for (int i = 0; i < 8; i++) {
            float4 v = p4[i];
            unsigned short h0,l0,h1,l1,h2,l2,h3,l3;
            split_bf16(v.x, h0, l0);
            split_bf16(v.y, h1, l1);
            split_bf16(v.z, h2, l2);
            split_bf16(v.w, h3, l3);
            int k = kbase + i*4;
            *(uint32_t*)&Ahi[r*APITCH + k]     = (uint32_t)h0 | ((uint32_t)h1 << 16);
            *(uint32_t*)&Ahi[r*APITCH + k + 2] = (uint32_t)h2 | ((uint32_t)h3 << 16);
            *(uint32_t*)&Alo[r*APITCH + k]     = (uint32_t)l0 | ((uint32_t)l1 << 16);
            *(uint32_t*)&Alo[r*APITCH + k + 2] = (uint32_t)l2 | ((uint32_t)l3 << 16);
        }
    }
}

// ================= K4: GEMM1 via mma.sync + fused gates =======================
__global__ __launch_bounds__(512) void k4_mma(const float* __restrict__ x,
                                              const float* __restrict__ bhid) {
    extern __shared__ unsigned short smu[];
    unsigned short* Ahi = smu;
    unsigned short* Alo = smu + 128*APITCH;
    int tid = threadIdx.x, lane = tid & 31, wid = tid >> 5;
    int row0 = blockIdx.x * 128;

    convert_A(Ahi, Alo, x, g_csum, row0, tid, 512);
    __syncthreads();

    int slab = wid >> 1, nhalf = wid & 1;
    int m0 = slab*16 + (lane >> 2);
    int kq = (lane & 3)*2;

    float c[12][4];
    #pragma unroll
    for (int j = 0; j < 12; j++)
        #pragma unroll
        for (int e = 0; e < 4; e++) c[j][e] = 0.f;

    #pragma unroll
    for (int ks = 0; ks < 8; ks++) {
        int ka = ks*16 + kq;
        uint32_t ah0 = *(const uint32_t*)&Ahi[m0*APITCH + ka];
        uint32_t ah1 = *(const uint32_t*)&Ahi[(m0+8)*APITCH + ka];
        uint32_t ah2 = *(const uint32_t*)&Ahi[m0*APITCH + ka + 8];
        uint32_t ah3 = *(const uint32_t*)&Ahi[(m0+8)*APITCH + ka + 8];
        uint32_t al0 = *(const uint32_t*)&Alo[m0*APITCH + ka];
        uint32_t al1 = *(const uint32_t*)&Alo[(m0+8)*APITCH + ka];
        uint32_t al2 = *(const uint32_t*)&Alo[m0*APITCH + ka + 8];
        uint32_t al3 = *(const uint32_t*)&Alo[(m0+8)*APITCH + ka + 8];
        const uint32_t* bbh = g_WhF_hi + ((size_t)(ks*24 + nhalf*12)*32 + lane)*2;
        const uint32_t* bbl = g_WhF_lo + ((size_t)(ks*24 + nhalf*12)*32 + lane)*2;
        #pragma unroll
        for (int nt = 0; nt < 12; nt++) {
            uint2 bh2 = *(const uint2*)(bbh + nt*64);
            uint2 bl2 = *(const uint2*)(bbl + nt*64);
            MMA4(c[nt], ah0, ah1, ah2, ah3, bh2.x, bh2.y);
            MMA4(c[nt], ah0, ah1, ah2, ah3, bl2.x, bl2.y);
            MMA4(c[nt], al0, al1, al2, al3, bh2.x, bh2.y);
        }
    }

    int u0 = (lane & 3)*2;
    int rbase = row0 + slab*16 + (lane >> 2);
    #pragma unroll
    for (int dt = 0; dt < 4; dt++) {
        int d = nhalf*32 + dt*8 + u0;
        float bi0 = bhid[d],       bi1 = bhid[d+1];
        float bf0 = bhid[64 + d],  bf1 = bhid[64 + d + 1];
        float bq0 = bhid[128 + d], bq1 = bhid[128 + d + 1];
        #pragma unroll
        for (int h = 0; h < 2; h++) {
            int row = rbase + h*8;
            float i0 = c[dt][h*2]   + bi0, i1 = c[dt][h*2+1]   + bi1;
            float f0 = c[dt+4][h*2] + bf0, f1 = c[dt+4][h*2+1] + bf1;
            float q0 = c[dt+8][h*2] + bq0, q1 = c[dt+8][h*2+1] + bq1;
            float2 vf, vi;
            vf.x = sigmoidf_(f0);
            vf.y = sigmoidf_(f1);
            vi.x = sigmoidf_(i0) * fmaxf(q0, 0.f);
            vi.y = sigmoidf_(i1) * fmaxf(q1, 0.f);
            *(float2*)&g_fg [(size_t)row*64 + d] = vf;
            *(float2*)&g_igh[(size_t)row*64 + d] = vi;
        }
    }
}

// ================= K7b: GEMM2 via mma.sync + fused output gate ================
__global__ __launch_bounds__(256) void k7b_mma(const float* __restrict__ x,
                                               const float* __restrict__ bog,
                                               float* __restrict__ out) {
    extern __shared__ unsigned short smu[];
    unsigned short* Ahi = smu;
    unsigned short* Alo = smu + 128*APITCH;
    int tid = threadIdx.x, lane = tid & 31, wid = tid >> 5;
    int row0 = blockIdx.x * 128;

    convert_A(Ahi, Alo, x, g_cell, row0, tid, 256);
    __syncthreads();

    int m0 = wid*16 + (lane >> 2);
    int kq = (lane & 3)*2;

    float c[8][4];
    #pragma unroll
    for (int j = 0; j < 8; j++)
        #pragma unroll
        for (int e = 0; e < 4; e++) c[j][e] = 0.f;

    #pragma unroll
    for (int ks = 0; ks < 8; ks++) {
        int ka = ks*16 + kq;
        uint32_t ah0 = *(const uint32_t*)&Ahi[m0*APITCH + ka];
        uint32_t ah1 = *(const uint32_t*)&Ahi[(m0+8)*APITCH + ka];
        uint32_t ah2 = *(const uint32_t*)&Ahi[m0*APITCH + ka + 8];
        uint32_t ah3 = *(const uint32_t*)&Ahi[(m0+8)*APITCH + ka + 8];
        uint32_t al0 = *(const uint32_t*)&Alo[m0*APITCH + ka];
        uint32_t al1 = *(const uint32_t*)&Alo[(m0+8)*APITCH + ka];
        uint32_t al2 = *(const uint32_t*)&Alo[m0*APITCH + ka + 8];
        uint32_t al3 = *(const uint32_t*)&Alo[(m0+8)*APITCH + ka + 8];
        const uint32_t* bbh = g_WoF_hi + ((size_t)(ks*8)*32 + lane)*2;
        const uint32_t* bbl = g_WoF_lo + ((size_t)(ks*8)*32 + lane)*2;
        #pragma unroll
        for (int nt = 0; nt < 8; nt++) {
            uint2 bh2 = *(const uint2*)(bbh + nt*64);
            uint2 bl2 = *(const uint2*)(bbl + nt*64);
            MMA4(c[nt], ah0, ah1, ah2, ah3, bh2.x, bh2.y);
            MMA4(c[nt], ah0, ah1, ah2, ah3, bl2.x, bl2.y);
            MMA4(c[nt], al0, al1, al2, al3, bh2.x, bh2.y);
        }
    }

    int u0 = (lane & 3)*2;
    int rbase = row0 + wid*16 + (lane >> 2);
    #pragma unroll
    for (int nt = 0; nt < 8; nt++) {
        int d = nt*8 + u0;
        float b0 = bog[d], b1 = bog[d+1];
        #pragma unroll
        for (int h = 0; h < 2; h++) {
            int row = rbase + h*8;
            float2 cv = *(const float2*)&g_cell[(size_t)row*64 + d];
            float2 ov;
            ov.x = sigmoidf_(c[nt][h*2]   + b0) * cv.x;
            ov.y = sigmoidf_(c[nt][h*2+1] + b1) * cv.y;
            *(float2*)&out[(size_t)row*64 + d] = ov;
        }
    }
}

// ================= launch =====================================================
extern "C" void kernel_launch(void* const* d_in, const int* in_sizes, int n_in,
                              void* d_out, int out_size) {
    const float* x      = (const float*)d_in[0];
    const float* Wh     = (const float*)d_in[1];
    const float* bh     = (const float*)d_in[2];
    const float* Wog    = (const float*)d_in[3];
    const float* bog    = (const float*)d_in[4];
    const float* gamma  = (const float*)d_in[5];
    const float* beta   = (const float*)d_in[6];
    const float* initcx = (const float*)d_in[7];
    float* out = (float*)d_out;

    static bool attr_done = false;
    if (!attr_done) {
        cudaFuncSetAttribute(k4_mma,  cudaFuncAttributeMaxDynamicSharedMemorySize, A_SMEM_BYTES);
        cudaFuncSetAttribute(k7b_mma, cudaFuncAttributeMaxDynamicSharedMemorySize, A_SMEM_BYTES);
        attr_done = true;
    }

    kprep_w<<<48, 256>>>(Wh, Wog);
    k1_chunksum<<<BC, 512>>>(x);
    k3_csum_ln<<<BC, 512>>>(x, gamma, beta);
    k4_mma<<<ROWS/128, 512, A_SMEM_BYTES>>>(x, bh);
    k5_chunkscan<<<BC, 512>>>();
    k7a_cell<<<BC, 512>>>(initcx);
    k7b_mma<<<ROWS/128, 256, A_SMEM_BYTES>>>(x, bog, out);
}

// round 7
// speedup vs baseline: 1.9480x; 1.2023x over previous
#include <cuda_runtime.h>
#include <cuda_bf16.h>
#include <cstdint>

// Problem dims
#define BB 4
#define SS 4096
#define HH 8
#define DD 64
#define HD 512
#define TOK (BB*SS)
#define ROWS (TOK*HH)          // 131072 gemm rows
#define CC 32
#define NC (SS/CC)
#define BC (BB*HD ? (BB*(SS/CC)) : 0)
#undef BC
#define BC (BB*NC)

// ================= scratch ====================================================
__device__ float g_csum[ROWS*DD];
__device__ float g_fg  [ROWS*DD];
__device__ float g_igh [ROWS*DD];
__device__ float g_cell[ROWS*DD];
__device__ float g_chunksum[BC*HD];
__device__ float g_A [BC*HD];
__device__ float g_Bv[BC*HD];
// W pre-packed in mma B-fragment order: [ks][nt][lane][2] u32 (bf16x2 each)
__device__ uint32_t g_WhF_hi[12288];   // GEMM1: 8 ks * 24 nt * 32 * 2
__device__ uint32_t g_WhF_lo[12288];
__device__ uint32_t g_WoF_hi[4096];    // GEMM2: 8 ks * 8 nt * 32 * 2
__device__ uint32_t g_WoF_lo[4096];

// ================= helpers ====================================================
__device__ __forceinline__ float sigmoidf_(float v) { return 1.f / (1.f + __expf(-v)); }

__device__ __forceinline__ void split_bf16(float v, unsigned short& hi, unsigned short& lo) {
    __nv_bfloat16 h = __float2bfloat16(v);
    __nv_bfloat16 l = __float2bfloat16(v - __bfloat162float(h));
    hi = __bfloat16_as_ushort(h);
    lo = __bfloat16_as_ushort(l);
}

#define MMA4(c, a0,a1,a2,a3, b0,b1) \
    asm volatile("mma.sync.aligned.m16n8k16.row.col.f32.bf16.bf16.f32 " \
        "{%0,%1,%2,%3}, {%4,%5,%6,%7}, {%8,%9}, {%0,%1,%2,%3};" \
        : "+f"((c)[0]),"+f"((c)[1]),"+f"((c)[2]),"+f"((c)[3]) \
        : "r"(a0),"r"(a1),"r"(a2),"r"(a3),"r"(b0),"r"(b1))

// ================= prep: W -> B-fragment images ===============================
// GEMM1 permutation (quarter-N warps): nt_global = nquad*6 + gate*2 + dt
//   d = nquad*16 + dt*8 + (lane>>2), n = gate*64 + d.
// Gate triple for d lives at c[dt], c[dt+2], c[dt+4] of one thread.
__global__ void kprep_w(const float* __restrict__ Wh, const float* __restrict__ Wog) {
    int t = blockIdx.x * blockDim.x + threadIdx.x;
    int stride = gridDim.x * blockDim.x;
    for (int idx = t; idx < 12288; idx += stride) {
        int reg  = idx & 1;
        int lane = (idx >> 1) & 31;
        int nt   = (idx >> 6) % 24;
        int ks   = (idx >> 6) / 24;
        int nquad = nt / 6, ntl = nt % 6;
        int gate = ntl >> 1, dt = ntl & 1;
        int d = nquad*16 + dt*8 + (lane >> 2);
        int n = gate*64 + d;
        int k0 = ks*16 + (lane & 3)*2 + reg*8;
        unsigned short h0, l0, h1, l1;
        split_bf16(Wh[(size_t)k0*192 + n], h0, l0);
        split_bf16(Wh[(size_t)(k0+1)*192 + n], h1, l1);
        g_WhF_hi[idx] = (uint32_t)h0 | ((uint32_t)h1 << 16);
        g_WhF_lo[idx] = (uint32_t)l0 | ((uint32_t)l1 << 16);
    }
    for (int idx = t; idx < 4096; idx += stride) {
        int reg  = idx & 1;
        int lane = (idx >> 1) & 31;
        int nt   = (idx >> 6) % 8;
        int ks   = (idx >> 6) / 8;
        int n = nt*8 + (lane >> 2);
        int k0 = ks*16 + (lane & 3)*2 + reg*8;
        unsigned short h0, l0, h1, l1;
        split_bf16(Wog[(size_t)k0*64 + n], h0, l0);
        split_bf16(Wog[(size_t)(k0+1)*64 + n], h1, l1);
        g_WoF_hi[idx] = (uint32_t)h0 | ((uint32_t)h1 << 16);
        g_WoF_lo[idx] = (uint32_t)l0 | ((uint32_t)l1 << 16);
    }
}

// ================= K1: per-chunk sums of X ------------------------------------
__global__ void k1_chunksum(const float* __restrict__ x) {
    int bc = blockIdx.x;
    int b = bc / NC, c = bc % NC;
    int tid = threadIdx.x;
    const float* p = x + ((size_t)(b*SS + c*CC))*HD + tid;
    float s = 0.f;
    #pragma unroll
    for (int i = 0; i < CC; i++) s += p[(size_t)i*HD];
    g_chunksum[(size_t)bc*HD + tid] = s;
}

// ================= K3: prefix lookback + cumsum + LayerNorm ==================
__global__ __launch_bounds__(512) void k3_csum_ln(const float* __restrict__ x,
                                                  const float* __restrict__ gamma,
                                                  const float* __restrict__ beta) {
    int bc = blockIdx.x;
    int b = bc / NC, c = bc % NC;
    int tid = threadIdx.x;
    int warp = tid >> 5, lane = tid & 31;
    __shared__ float sm_s[16][33];
    __shared__ float sm_q[16][33];
    __shared__ float sm_mean[32], sm_inv[32];

    float run = 0.f;
    {
        const float* pcs = g_chunksum + (size_t)b*NC*HD + tid;
        int j = 0;
        for (; j + 4 <= c; j += 4)
            run += pcs[(size_t)(j+0)*HD] + pcs[(size_t)(j+1)*HD]
                 + pcs[(size_t)(j+2)*HD] + pcs[(size_t)(j+3)*HD];
        for (; j < c; j++) run += pcs[(size_t)j*HD];
    }

    float ga = gamma[tid], be = beta[tid];
    size_t base = ((size_t)(b*SS + c*CC))*HD + tid;
    const float* px = x + base;
    float* pc = g_csum + base;

    float r1 = run;
    #pragma unroll
    for (int i = 0; i < CC; i++) {
        float val = r1;
        r1 += px[(size_t)i*HD];
        float s = val, q = val*val;
        #pragma unroll
        for (int o = 16; o; o >>= 1) {
            s += __shfl_xor_sync(0xffffffffu, s, o);
            q += __shfl_xor_sync(0xffffffffu, q, o);
        }
        if (lane == 0) { sm_s[warp][i] = s; sm_q[warp][i] = q; }
    }
    __syncthreads();

    {
        int t = tid >> 4, k = tid & 15;
        float s = sm_s[k][t], q = sm_q[k][t];
        #pragma unroll
        for (int o = 8; o; o >>= 1) {
            s += __shfl_xor_sync(0xffffffffu, s, o);
            q += __shfl_xor_sync(0xffffffffu, q, o);
        }
        if (k == 0) {
            float m = s * (1.f/512.f);
            float v = q * (1.f/512.f) - m*m;
            sm_mean[t] = m;
            sm_inv[t]  = rsqrtf(v + 1e-5f);
        }
    }
    __syncthreads();

    float r2 = run;
    #pragma unroll
    for (int i = 0; i < CC; i++) {
        float val = r2;
        r2 += px[(size_t)i*HD];
        pc[(size_t)i*HD] = (val - sm_mean[i]) * sm_inv[i] * ga + be;
    }
}

// ================= K5: per-chunk cell-scan states =============================
__global__ void k5_chunkscan() {
    int bc = blockIdx.x;
    int b = bc / NC, c = bc % NC;
    int tid = threadIdx.x;
    size_t base = ((size_t)(b*SS + c*CC))*HD + tid;
    const float* pf = g_fg + base;
    const float* pg = g_igh + base;
    float a = 1.f, bv = 0.f;
    #pragma unroll
    for (int i = 0; i < CC; i++) {
        float f = pf[(size_t)i*HD], g = pg[(size_t)i*HD];
        a *= f;
        bv = bv * f + g;
    }
    g_A [(size_t)bc*HD + tid] = a;
    g_Bv[(size_t)bc*HD + tid] = bv;
}

// ================= K7a: lookback carry + replay cell ==========================
__global__ void k7a_cell(const float* __restrict__ initcx) {
    int bc = blockIdx.x;
    int b = bc / NC, c = bc % NC;
    int tid = threadIdx.x;

    float carry = initcx[tid];
    {
        const float* pA = g_A  + (size_t)b*NC*HD + tid;
        const float* pB = g_Bv + (size_t)b*NC*HD + tid;
        #pragma unroll 4
        for (int j = 0; j < c; j++)
            carry = pA[(size_t)j*HD] * carry + pB[(size_t)j*HD];
    }

    size_t base = ((size_t)(b*SS + c*CC))*HD + tid;
    const float* pf = g_fg + base;
    const float* pg = g_igh + base;
    float* pc = g_cell + base;
    float cell = carry;
    #pragma unroll
    for (int i = 0; i < CC; i++) {
        cell = pf[(size_t)i*HD] * cell + pg[(size_t)i*HD];
        pc[(size_t)i*HD] = cell;
    }
}

// ================= A tile convert: f32 -> bf16 hi/lo in SMEM ==================
#define APITCH 136
#define A64_SMEM_BYTES (2*64*APITCH*2)    // 34816
#define A128_SMEM_BYTES (2*128*APITCH*2)  // 69632

// 64-row tile, 512 threads: r = tid>>3, k-eighth = tid&7 (16 k each).
__device__ __forceinline__ void convert_A64(unsigned short* Ahi, unsigned short* Alo,
                                            const float* __restrict__ x,
                                            const float* __restrict__ other,
                                            int row0, int tid) {
    int r = tid >> 3;
    int q = tid & 7;
    const float* src = (q < 4)
        ? (x     + (size_t)(row0 + r)*64 + q*16)
        : (other + (size_t)(row0 + r)*64 + (q-4)*16);
    int kbase = q*16;
    const float4* p4 = (const float4*)src;
    #pragma unroll
    for (int i = 0; i < 4; i++) {
        float4 v = p4[i];
        unsigned short h0,l0,h1,l1,h2,l2,h3,l3;
        split_bf16(v.x, h0, l0);
        split_bf16(v.y, h1, l1);
        split_bf16(v.z, h2, l2);
        split_bf16(v.w, h3, l3);
        int k = kbase + i*4;
        *(uint32_t*)&Ahi[r*APITCH + k]     = (uint32_t)h0 | ((uint32_t)h1 << 16);
        *(uint32_t*)&Ahi[r*APITCH + k + 2] = (uint32_t)h2 | ((uint32_t)h3 << 16);
        *(uint32_t*)&Alo[r*APITCH + k]     = (uint32_t)l0 | ((uint32_t)l1 << 16);
        *(uint32_t*)&Alo[r*APITCH + k + 2] = (uint32_t)l2 | ((uint32_t)l3 << 16);
    }
}

// 128-row tile, 512 threads: r = tid>>2, k-quarter = tid&3 (32 k each).
__device__ __forceinline__ void convert_A128(unsigned short* Ahi, unsigned short* Alo,
                                             const float* __restrict__ x,
                                             const float* __restrict__ other,
                                             int row0, int tid) {
    int r = tid >> 2;
    int q = tid & 3;
    const float* src = (q < 2)
        ? (x     + (size_t)(row0 + r)*64 + q*32)
        : (other + (size_t)(row0 + r)*64 + (q-2)*32);
    int kbase = q*32;
    const float4* p4 = (const float4*)src;
    #pragma unroll
    for (int i = 0; i < 8; i++) {
        float4 v = p4[i];
        unsigned short h0,l0,h1,l1,h2,l2,h3,l3;
        split_bf16(v.x, h0, l0);
        split_bf16(v.y, h1, l1);
        split_bf16(v.z, h2, l2);
        split_bf16(v.w, h3, l3);
        int k = kbase + i*4;
        *(uint32_t*)&Ahi[r*APITCH + k]     = (uint32_t)h0 | ((uint32_t)h1 << 16);
        *(uint32_t*)&Ahi[r*APITCH + k + 2] = (uint32_t)h2 | ((uint32_t)h3 << 16);
        *(uint32_t*)&Alo[r*APITCH + k]     = (uint32_t)l0 | ((uint32_t)l1 << 16);
        *(uint32_t*)&Alo[r*APITCH + k + 2] = (uint32_t)l2 | ((uint32_t)l3 << 16);
    }
}

// ================= K4: GEMM1 via mma.sync + fused gates =======================
// Block: 512 thr (16 warps), M-tile 64. Warp = slab(4)*16 rows x nquad(4)*48 cols.
__global__ __launch_bounds__(512, 2) void k4_mma(const float* __restrict__ x,
                                                 const float* __restrict__ bhid) {
    extern __shared__ unsigned short smu[];
    unsigned short* Ahi = smu;
    unsigned short* Alo = smu + 64*APITCH;
    int tid = threadIdx.x, lane = tid & 31, wid = tid >> 5;
    int row0 = blockIdx.x * 64;

    convert_A64(Ahi, Alo, x, g_csum, row0, tid);
    __syncthreads();

    int slab = wid >> 2, nquad = wid & 3;
    int m0 = slab*16 + (lane >> 2);
    int kq = (lane & 3)*2;

    float c[6][4];
    #pragma unroll
    for (int j = 0; j < 6; j++)
        #pragma unroll
        for (int e = 0; e < 4; e++) c[j][e] = 0.f;

    #pragma unroll
    for (int ks = 0; ks < 8; ks++) {
        int ka = ks*16 + kq;
        uint32_t ah0 = *(const uint32_t*)&Ahi[m0*APITCH + ka];
        uint32_t ah1 = *(const uint32_t*)&Ahi[(m0+8)*APITCH + ka];
        uint32_t ah2 = *(const uint32_t*)&Ahi[m0*APITCH + ka + 8];
        uint32_t ah3 = *(const uint32_t*)&Ahi[(m0+8)*APITCH + ka + 8];
        uint32_t al0 = *(const uint32_t*)&Alo[m0*APITCH + ka];
        uint32_t al1 = *(const uint32_t*)&Alo[(m0+8)*APITCH + ka];
        uint32_t al2 = *(const uint32_t*)&Alo[m0*APITCH + ka + 8];
        uint32_t al3 = *(const uint32_t*)&Alo[(m0+8)*APITCH + ka + 8];
        const uint32_t* bbh = g_WhF_hi + ((size_t)(ks*24 + nquad*6)*32 + lane)*2;
        const uint32_t* bbl = g_WhF_lo + ((size_t)(ks*24 + nquad*6)*32 + lane)*2;
        #pragma unroll
        for (int nt = 0; nt < 6; nt++) {
            uint2 bh2 = *(const uint2*)(bbh + nt*64);
            uint2 bl2 = *(const uint2*)(bbl + nt*64);
            MMA4(c[nt], ah0, ah1, ah2, ah3, bh2.x, bh2.y);
            MMA4(c[nt], ah0, ah1, ah2, ah3, bl2.x, bl2.y);
            MMA4(c[nt], al0, al1, al2, al3, bh2.x, bh2.y);
        }
    }

    // epilogue: gate triple for d at c[dt], c[dt+2], c[dt+4]
    int u0 = (lane & 3)*2;
    int rbase = row0 + slab*16 + (lane >> 2);
    #pragma unroll
    for (int dt = 0; dt < 2; dt++) {
        int d = nquad*16 + dt*8 + u0;
        float bi0 = bhid[d],       bi1 = bhid[d+1];
        float bf0 = bhid[64 + d],  bf1 = bhid[64 + d + 1];
        float bq0 = bhid[128 + d], bq1 = bhid[128 + d + 1];
        #pragma unroll
        for (int h = 0; h < 2; h++) {
            int row = rbase + h*8;
            float i0 = c[dt][h*2]   + bi0, i1 = c[dt][h*2+1]   + bi1;
            float f0 = c[dt+2][h*2] + bf0, f1 = c[dt+2][h*2+1] + bf1;
            float q0 = c[dt+4][h*2] + bq0, q1 = c[dt+4][h*2+1] + bq1;
            float2 vf, vi;
            vf.x = sigmoidf_(f0);
            vf.y = sigmoidf_(f1);
            vi.x = sigmoidf_(i0) * fmaxf(q0, 0.f);
            vi.y = sigmoidf_(i1) * fmaxf(q1, 0.f);
            *(float2*)&g_fg [(size_t)row*64 + d] = vf;
            *(float2*)&g_igh[(size_t)row*64 + d] = vi;
        }
    }
}

// ================= K7b: GEMM2 via mma.sync + fused output gate ================
// Block: 512 thr (16 warps), M-tile 128. Warp = slab(8)*16 rows x nhalf(2)*32 cols.
__global__ __launch_bounds__(512, 2) void k7b_mma(const float* __restrict__ x,
                                                  const float* __restrict__ bog,
                                                  float* __restrict__ out) {
    extern __shared__ unsigned short smu[];
    unsigned short* Ahi = smu;
    unsigned short* Alo = smu + 128*APITCH;
    int tid = threadIdx.x, lane = tid & 31, wid = tid >> 5;
    int row0 = blockIdx.x * 128;

    convert_A128(Ahi, Alo, x, g_cell, row0, tid);
    __syncthreads();

    int slab = wid >> 1, nhalf = wid & 1;
    int m0 = slab*16 + (lane >> 2);
    int kq = (lane & 3)*2;

    float c[4][4];
    #pragma unroll
    for (int j = 0; j < 4; j++)
        #pragma unroll
        for (int e = 0; e < 4; e++) c[j][e] = 0.f;

    #pragma unroll
    for (int ks = 0; ks < 8; ks++) {
        int ka = ks*16 + kq;
        uint32_t ah0 = *(const uint32_t*)&Ahi[m0*APITCH + ka];
        uint32_t ah1 = *(const uint32_t*)&Ahi[(m0+8)*APITCH + ka];
        uint32_t ah2 = *(const uint32_t*)&Ahi[m0*APITCH + ka + 8];
        uint32_t ah3 = *(const uint32_t*)&Ahi[(m0+8)*APITCH + ka + 8];
        uint32_t al0 = *(const uint32_t*)&Alo[m0*APITCH + ka];
        uint32_t al1 = *(const uint32_t*)&Alo[(m0+8)*APITCH + ka];
        uint32_t al2 = *(const uint32_t*)&Alo[m0*APITCH + ka + 8];
        uint32_t al3 = *(const uint32_t*)&Alo[(m0+8)*APITCH + ka + 8];
        const uint32_t* bbh = g_WoF_hi + ((size_t)(ks*8 + nhalf*4)*32 + lane)*2;
        const uint32_t* bbl = g_WoF_lo + ((size_t)(ks*8 + nhalf*4)*32 + lane)*2;
        #pragma unroll
        for (int nt = 0; nt < 4; nt++) {
            uint2 bh2 = *(const uint2*)(bbh + nt*64);
            uint2 bl2 = *(const uint2*)(bbl + nt*64);
            MMA4(c[nt], ah0, ah1, ah2, ah3, bh2.x, bh2.y);
            MMA4(c[nt], ah0, ah1, ah2, ah3, bl2.x, bl2.y);
            MMA4(c[nt], al0, al1, al2, al3, bh2.x, bh2.y);
        }
    }

    int u0 = (lane & 3)*2;
    int rbase = row0 + slab*16 + (lane >> 2);
    #pragma unroll
    for (int nt = 0; nt < 4; nt++) {
        int d = (nhalf*4 + nt)*8 + u0;
        float b0 = bog[d], b1 = bog[d+1];
        #pragma unroll
        for (int h = 0; h < 2; h++) {
            int row = rbase + h*8;
            float2 cv = *(const float2*)&g_cell[(size_t)row*64 + d];
            float2 ov;
            ov.x = sigmoidf_(c[nt][h*2]   + b0) * cv.x;
            ov.y = sigmoidf_(c[nt][h*2+1] + b1) * cv.y;
            *(float2*)&out[(size_t)row*64 + d] = ov;
        }
    }
}

// ================= launch =====================================================
extern "C" void kernel_launch(void* const* d_in, const int* in_sizes, int n_in,
                              void* d_out, int out_size) {
    const float* x      = (const float*)d_in[0];
    const float* Wh     = (const float*)d_in[1];
    const float* bh     = (const float*)d_in[2];
    const float* Wog    = (const float*)d_in[3];
    const float* bog    = (const float*)d_in[4];
    const float* gamma  = (const float*)d_in[5];
    const float* beta   = (const float*)d_in[6];
    const float* initcx = (const float*)d_in[7];
    float* out = (float*)d_out;

    static bool attr_done = false;
    if (!attr_done) {
        cudaFuncSetAttribute(k4_mma,  cudaFuncAttributeMaxDynamicSharedMemorySize, A64_SMEM_BYTES);
        cudaFuncSetAttribute(k7b_mma, cudaFuncAttributeMaxDynamicSharedMemorySize, A128_SMEM_BYTES);
        attr_done = true;
    }

    kprep_w<<<48, 256>>>(Wh, Wog);
    k1_chunksum<<<BC, 512>>>(x);
    k3_csum_ln<<<BC, 512>>>(x, gamma, beta);
    k4_mma<<<ROWS/64, 512, A64_SMEM_BYTES>>>(x, bh);
    k5_chunkscan<<<BC, 512>>>();
    k7a_cell<<<BC, 512>>>(initcx);
    k7b_mma<<<ROWS/128, 512, A128_SMEM_BYTES>>>(x, bog, out);
}

// round 8
// speedup vs baseline: 2.1460x; 1.1016x over previous
#include <cuda_runtime.h>
#include <cuda_bf16.h>
#include <cuda_fp16.h>
#include <cstdint>

// Problem dims
#define BB 4
#define SS 4096
#define HH 8
#define DD 64
#define HD 512
#define TOK (BB*SS)
#define ROWS (TOK*HH)          // 131072 gemm rows
#define CC 32
#define NC (SS/CC)
#define BC (BB*NC)

// ================= scratch ====================================================
__device__ float g_csum[ROWS*DD];
__device__ float g_fg  [ROWS*DD];
__device__ float g_igh [ROWS*DD];
__device__ float g_cell[ROWS*DD];
__device__ float g_chunksum[BC*HD];
__device__ float g_A [BC*HD];
__device__ float g_Bv[BC*HD];
// W pre-packed in mma B-fragment order: [ks][nt][lane][2] u32 (fp16x2 each)
__device__ uint32_t g_WhF[12288];   // GEMM1: 8 ks * 24 nt * 32 * 2
__device__ uint32_t g_WoF[4096];    // GEMM2: 8 ks * 8 nt * 32 * 2

// ================= helpers ====================================================
__device__ __forceinline__ float sigmoidf_(float v) { return 1.f / (1.f + __expf(-v)); }

__device__ __forceinline__ void split_f16(float v, unsigned short& hi, unsigned short& lo) {
    __half h = __float2half_rn(v);
    __half l = __float2half_rn(v - __half2float(h));
    hi = __half_as_ushort(h);
    lo = __half_as_ushort(l);
}

#define MMA4(c, a0,a1,a2,a3, b0,b1) \
    asm volatile("mma.sync.aligned.m16n8k16.row.col.f32.f16.f16.f32 " \
        "{%0,%1,%2,%3}, {%4,%5,%6,%7}, {%8,%9}, {%0,%1,%2,%3};" \
        : "+f"((c)[0]),"+f"((c)[1]),"+f"((c)[2]),"+f"((c)[3]) \
        : "r"(a0),"r"(a1),"r"(a2),"r"(a3),"r"(b0),"r"(b1))

// ================= prep: W -> B-fragment images (fp16, single-rounded) ========
// GEMM1 permutation (quarter-N warps): nt_global = nquad*6 + gate*2 + dt
//   d = nquad*16 + dt*8 + (lane>>2), n = gate*64 + d.
// Gate triple for d lives at c[dt], c[dt+2], c[dt+4] of one thread.
__global__ void kprep_w(const float* __restrict__ Wh, const float* __restrict__ Wog) {
    int t = blockIdx.x * blockDim.x + threadIdx.x;
    int stride = gridDim.x * blockDim.x;
    for (int idx = t; idx < 12288; idx += stride) {
        int reg  = idx & 1;
        int lane = (idx >> 1) & 31;
        int nt   = (idx >> 6) % 24;
        int ks   = (idx >> 6) / 24;
        int nquad = nt / 6, ntl = nt % 6;
        int gate = ntl >> 1, dt = ntl & 1;
        int d = nquad*16 + dt*8 + (lane >> 2);
        int n = gate*64 + d;
        int k0 = ks*16 + (lane & 3)*2 + reg*8;
        unsigned short h0 = __half_as_ushort(__float2half_rn(Wh[(size_t)k0*192 + n]));
        unsigned short h1 = __half_as_ushort(__float2half_rn(Wh[(size_t)(k0+1)*192 + n]));
        g_WhF[idx] = (uint32_t)h0 | ((uint32_t)h1 << 16);
    }
    for (int idx = t; idx < 4096; idx += stride) {
        int reg  = idx & 1;
        int lane = (idx >> 1) & 31;
        int nt   = (idx >> 6) % 8;
        int ks   = (idx >> 6) / 8;
        int n = nt*8 + (lane >> 2);
        int k0 = ks*16 + (lane & 3)*2 + reg*8;
        unsigned short h0 = __half_as_ushort(__float2half_rn(Wog[(size_t)k0*64 + n]));
        unsigned short h1 = __half_as_ushort(__float2half_rn(Wog[(size_t)(k0+1)*64 + n]));
        g_WoF[idx] = (uint32_t)h0 | ((uint32_t)h1 << 16);
    }
}

// ================= K1: per-chunk sums of X ------------------------------------
__global__ void k1_chunksum(const float* __restrict__ x) {
    int bc = blockIdx.x;
    int b = bc / NC, c = bc % NC;
    int tid = threadIdx.x;
    const float* p = x + ((size_t)(b*SS + c*CC))*HD + tid;
    float s = 0.f;
    #pragma unroll
    for (int i = 0; i < CC; i++) s += p[(size_t)i*HD];
    g_chunksum[(size_t)bc*HD + tid] = s;
}

// ================= K3: prefix lookback + cumsum + LayerNorm ==================
__global__ __launch_bounds__(512) void k3_csum_ln(const float* __restrict__ x,
                                                  const float* __restrict__ gamma,
                                                  const float* __restrict__ beta) {
    int bc = blockIdx.x;
    int b = bc / NC, c = bc % NC;
    int tid = threadIdx.x;
    int warp = tid >> 5, lane = tid & 31;
    __shared__ float sm_s[16][33];
    __shared__ float sm_q[16][33];
    __shared__ float sm_mean[32], sm_inv[32];

    float run = 0.f;
    {
        const float* pcs = g_chunksum + (size_t)b*NC*HD + tid;
        int j = 0;
        for (; j + 4 <= c; j += 4)
            run += pcs[(size_t)(j+0)*HD] + pcs[(size_t)(j+1)*HD]
                 + pcs[(size_t)(j+2)*HD] + pcs[(size_t)(j+3)*HD];
        for (; j < c; j++) run += pcs[(size_t)j*HD];
    }

    float ga = gamma[tid], be = beta[tid];
    size_t base = ((size_t)(b*SS + c*CC))*HD + tid;
    const float* px = x + base;
    float* pc = g_csum + base;

    float r1 = run;
    #pragma unroll
    for (int i = 0; i < CC; i++) {
        float val = r1;
        r1 += px[(size_t)i*HD];
        float s = val, q = val*val;
        #pragma unroll
        for (int o = 16; o; o >>= 1) {
            s += __shfl_xor_sync(0xffffffffu, s, o);
            q += __shfl_xor_sync(0xffffffffu, q, o);
        }
        if (lane == 0) { sm_s[warp][i] = s; sm_q[warp][i] = q; }
    }
    __syncthreads();

    {
        int t = tid >> 4, k = tid & 15;
        float s = sm_s[k][t], q = sm_q[k][t];
        #pragma unroll
        for (int o = 8; o; o >>= 1) {
            s += __shfl_xor_sync(0xffffffffu, s, o);
            q += __shfl_xor_sync(0xffffffffu, q, o);
        }
        if (k == 0) {
            float m = s * (1.f/512.f);
            float v = q * (1.f/512.f) - m*m;
            sm_mean[t] = m;
            sm_inv[t]  = rsqrtf(v + 1e-5f);
        }
    }
    __syncthreads();

    float r2 = run;
    #pragma unroll
    for (int i = 0; i < CC; i++) {
        float val = r2;
        r2 += px[(size_t)i*HD];
        pc[(size_t)i*HD] = (val - sm_mean[i]) * sm_inv[i] * ga + be;
    }
}

// ================= K5: per-chunk cell-scan states =============================
__global__ void k5_chunkscan() {
    int bc = blockIdx.x;
    int b = bc / NC, c = bc % NC;
    int tid = threadIdx.x;
    size_t base = ((size_t)(b*SS + c*CC))*HD + tid;
    const float* pf = g_fg + base;
    const float* pg = g_igh + base;
    float a = 1.f, bv = 0.f;
    #pragma unroll
    for (int i = 0; i < CC; i++) {
        float f = pf[(size_t)i*HD], g = pg[(size_t)i*HD];
        a *= f;
        bv = bv * f + g;
    }
    g_A [(size_t)bc*HD + tid] = a;
    g_Bv[(size_t)bc*HD + tid] = bv;
}

// ================= K7a: lookback carry + replay cell ==========================
__global__ void k7a_cell(const float* __restrict__ initcx) {
    int bc = blockIdx.x;
    int b = bc / NC, c = bc % NC;
    int tid = threadIdx.x;

    float carry = initcx[tid];
    {
        const float* pA = g_A  + (size_t)b*NC*HD + tid;
        const float* pB = g_Bv + (size_t)b*NC*HD + tid;
        #pragma unroll 4
        for (int j = 0; j < c; j++)
            carry = pA[(size_t)j*HD] * carry + pB[(size_t)j*HD];
    }

    size_t base = ((size_t)(b*SS + c*CC))*HD + tid;
    const float* pf = g_fg + base;
    const float* pg = g_igh + base;
    float* pc = g_cell + base;
    float cell = carry;
    #pragma unroll
    for (int i = 0; i < CC; i++) {
        cell = pf[(size_t)i*HD] * cell + pg[(size_t)i*HD];
        pc[(size_t)i*HD] = cell;
    }
}

// ================= A tile convert: f32 -> fp16 hi/lo in SMEM ==================
#define APITCH 136
#define A64_SMEM_BYTES (2*64*APITCH*2)    // 34816
#define A128_SMEM_BYTES (2*128*APITCH*2)  // 69632

// 64-row tile, 512 threads: r = tid>>3, k-eighth = tid&7 (16 k each).
__device__ __forceinline__ void convert_A64(unsigned short* Ahi, unsigned short* Alo,
                                            const float* __restrict__ x,
                                            const float* __restrict__ other,
                                            int row0, int tid) {
    int r = tid >> 3;
    int q = tid & 7;
    const float* src = (q < 4)
        ? (x     + (size_t)(row0 + r)*64 + q*16)
        : (other + (size_t)(row0 + r)*64 + (q-4)*16);
    int kbase = q*16;
    const float4* p4 = (const float4*)src;
    #pragma unroll
    for (int i = 0; i < 4; i++) {
        float4 v = p4[i];
        unsigned short h0,l0,h1,l1,h2,l2,h3,l3;
        split_f16(v.x, h0, l0);
        split_f16(v.y, h1, l1);
        split_f16(v.z, h2, l2);
        split_f16(v.w, h3, l3);
        int k = kbase + i*4;
        *(uint32_t*)&Ahi[r*APITCH + k]     = (uint32_t)h0 | ((uint32_t)h1 << 16);
        *(uint32_t*)&Ahi[r*APITCH + k + 2] = (uint32_t)h2 | ((uint32_t)h3 << 16);
        *(uint32_t*)&Alo[r*APITCH + k]     = (uint32_t)l0 | ((uint32_t)l1 << 16);
        *(uint32_t*)&Alo[r*APITCH + k + 2] = (uint32_t)l2 | ((uint32_t)l3 << 16);
    }
}

// 128-row tile, 512 threads: r = tid>>2, k-quarter = tid&3 (32 k each).
__device__ __forceinline__ void convert_A128(unsigned short* Ahi, unsigned short* Alo,
                                             const float* __restrict__ x,
                                             const float* __restrict__ other,
                                             int row0, int tid) {
    int r = tid >> 2;
    int q = tid & 3;
    const float* src = (q < 2)
        ? (x     + (size_t)(row0 + r)*64 + q*32)
        : (other + (size_t)(row0 + r)*64 + (q-2)*32);
    int kbase = q*32;
    const float4* p4 = (const float4*)src;
    #pragma unroll
    for (int i = 0; i < 8; i++) {
        float4 v = p4[i];
        unsigned short h0,l0,h1,l1,h2,l2,h3,l3;
        split_f16(v.x, h0, l0);
        split_f16(v.y, h1, l1);
        split_f16(v.z, h2, l2);
        split_f16(v.w, h3, l3);
        int k = kbase + i*4;
        *(uint32_t*)&Ahi[r*APITCH + k]     = (uint32_t)h0 | ((uint32_t)h1 << 16);
        *(uint32_t*)&Ahi[r*APITCH + k + 2] = (uint32_t)h2 | ((uint32_t)h3 << 16);
        *(uint32_t*)&Alo[r*APITCH + k]     = (uint32_t)l0 | ((uint32_t)l1 << 16);
        *(uint32_t*)&Alo[r*APITCH + k + 2] = (uint32_t)l2 | ((uint32_t)l3 << 16);
    }
}

// ================= K4: GEMM1 via mma.sync + fused gates =======================
// Block: 512 thr (16 warps), M-tile 64. Warp = slab(4)*16 rows x nquad(4)*48 cols.
__global__ __launch_bounds__(512, 2) void k4_mma(const float* __restrict__ x,
                                                 const float* __restrict__ bhid) {
    extern __shared__ unsigned short smu[];
    unsigned short* Ahi = smu;
    unsigned short* Alo = smu + 64*APITCH;
    int tid = threadIdx.x, lane = tid & 31, wid = tid >> 5;
    int row0 = blockIdx.x * 64;

    convert_A64(Ahi, Alo, x, g_csum, row0, tid);
    __syncthreads();

    int slab = wid >> 2, nquad = wid & 3;
    int m0 = slab*16 + (lane >> 2);
    int kq = (lane & 3)*2;

    float c[6][4];
    #pragma unroll
    for (int j = 0; j < 6; j++)
        #pragma unroll
        for (int e = 0; e < 4; e++) c[j][e] = 0.f;

    #pragma unroll
    for (int ks = 0; ks < 8; ks++) {
        int ka = ks*16 + kq;
        uint32_t ah0 = *(const uint32_t*)&Ahi[m0*APITCH + ka];
        uint32_t ah1 = *(const uint32_t*)&Ahi[(m0+8)*APITCH + ka];
        uint32_t ah2 = *(const uint32_t*)&Ahi[m0*APITCH + ka + 8];
        uint32_t ah3 = *(const uint32_t*)&Ahi[(m0+8)*APITCH + ka + 8];
        uint32_t al0 = *(const uint32_t*)&Alo[m0*APITCH + ka];
        uint32_t al1 = *(const uint32_t*)&Alo[(m0+8)*APITCH + ka];
        uint32_t al2 = *(const uint32_t*)&Alo[m0*APITCH + ka + 8];
        uint32_t al3 = *(const uint32_t*)&Alo[(m0+8)*APITCH + ka + 8];
        const uint32_t* bb = g_WhF + ((size_t)(ks*24 + nquad*6)*32 + lane)*2;
        #pragma unroll
        for (int nt = 0; nt < 6; nt++) {
            uint2 b2 = *(const uint2*)(bb + nt*64);
            MMA4(c[nt], ah0, ah1, ah2, ah3, b2.x, b2.y);
            MMA4(c[nt], al0, al1, al2, al3, b2.x, b2.y);
        }
    }

    // epilogue: gate triple for d at c[dt], c[dt+2], c[dt+4]
    int u0 = (lane & 3)*2;
    int rbase = row0 + slab*16 + (lane >> 2);
    #pragma unroll
    for (int dt = 0; dt < 2; dt++) {
        int d = nquad*16 + dt*8 + u0;
        float bi0 = bhid[d],       bi1 = bhid[d+1];
        float bf0 = bhid[64 + d],  bf1 = bhid[64 + d + 1];
        float bq0 = bhid[128 + d], bq1 = bhid[128 + d + 1];
        #pragma unroll
        for (int h = 0; h < 2; h++) {
            int row = rbase + h*8;
            float i0 = c[dt][h*2]   + bi0, i1 = c[dt][h*2+1]   + bi1;
            float f0 = c[dt+2][h*2] + bf0, f1 = c[dt+2][h*2+1] + bf1;
            float q0 = c[dt+4][h*2] + bq0, q1 = c[dt+4][h*2+1] + bq1;
            float2 vf, vi;
            vf.x = sigmoidf_(f0);
            vf.y = sigmoidf_(f1);
            vi.x = sigmoidf_(i0) * fmaxf(q0, 0.f);
            vi.y = sigmoidf_(i1) * fmaxf(q1, 0.f);
            *(float2*)&g_fg [(size_t)row*64 + d] = vf;
            *(float2*)&g_igh[(size_t)row*64 + d] = vi;
        }
    }
}

// ================= K7b: GEMM2 via mma.sync + fused output gate ================
// Block: 512 thr (16 warps), M-tile 128. Warp = slab(8)*16 rows x nhalf(2)*32 cols.
__global__ __launch_bounds__(512, 2) void k7b_mma(const float* __restrict__ x,
                                                  const float* __restrict__ bog,
                                                  float* __restrict__ out) {
    extern __shared__ unsigned short smu[];
    unsigned short* Ahi = smu;
    unsigned short* Alo = smu + 128*APITCH;
    int tid = threadIdx.x, lane = tid & 31, wid = tid >> 5;
    int row0 = blockIdx.x * 128;

    convert_A128(Ahi, Alo, x, g_cell, row0, tid);
    __syncthreads();

    int slab = wid >> 1, nhalf = wid & 1;
    int m0 = slab*16 + (lane >> 2);
    int kq = (lane & 3)*2;

    float c[4][4];
    #pragma unroll
    for (int j = 0; j < 4; j++)
        #pragma unroll
        for (int e = 0; e < 4; e++) c[j][e] = 0.f;

    #pragma unroll
    for (int ks = 0; ks < 8; ks++) {
        int ka = ks*16 + kq;
        uint32_t ah0 = *(const uint32_t*)&Ahi[m0*APITCH + ka];
        uint32_t ah1 = *(const uint32_t*)&Ahi[(m0+8)*APITCH + ka];
        uint32_t ah2 = *(const uint32_t*)&Ahi[m0*APITCH + ka + 8];
        uint32_t ah3 = *(const uint32_t*)&Ahi[(m0+8)*APITCH + ka + 8];
        uint32_t al0 = *(const uint32_t*)&Alo[m0*APITCH + ka];
        uint32_t al1 = *(const uint32_t*)&Alo[(m0+8)*APITCH + ka];
        uint32_t al2 = *(const uint32_t*)&Alo[m0*APITCH + ka + 8];
        uint32_t al3 = *(const uint32_t*)&Alo[(m0+8)*APITCH + ka + 8];
        const uint32_t* bb = g_WoF + ((size_t)(ks*8 + nhalf*4)*32 + lane)*2;
        #pragma unroll
        for (int nt = 0; nt < 4; nt++) {
            uint2 b2 = *(const uint2*)(bb + nt*64);
            MMA4(c[nt], ah0, ah1, ah2, ah3, b2.x, b2.y);
            MMA4(c[nt], al0, al1, al2, al3, b2.x, b2.y);
        }
    }

    int u0 = (lane & 3)*2;
    int rbase = row0 + slab*16 + (lane >> 2);
    #pragma unroll
    for (int nt = 0; nt < 4; nt++) {
        int d = (nhalf*4 + nt)*8 + u0;
        float b0 = bog[d], b1 = bog[d+1];
        #pragma unroll
        for (int h = 0; h < 2; h++) {
            int row = rbase + h*8;
            float2 cv = *(const float2*)&g_cell[(size_t)row*64 + d];
            float2 ov;
            ov.x = sigmoidf_(c[nt][h*2]   + b0) * cv.x;
            ov.y = sigmoidf_(c[nt][h*2+1] + b1) * cv.y;
            *(float2*)&out[(size_t)row*64 + d] = ov;
        }
    }
}

// ================= launch =====================================================
extern "C" void kernel_launch(void* const* d_in, const int* in_sizes, int n_in,
                              void* d_out, int out_size) {
    const float* x      = (const float*)d_in[0];
    const float* Wh     = (const float*)d_in[1];
    const float* bh     = (const float*)d_in[2];
    const float* Wog    = (const float*)d_in[3];
    const float* bog    = (const float*)d_in[4];
    const float* gamma  = (const float*)d_in[5];
    const float* beta   = (const float*)d_in[6];
    const float* initcx = (const float*)d_in[7];
    float* out = (float*)d_out;

    static bool attr_done = false;
    if (!attr_done) {
        cudaFuncSetAttribute(k4_mma,  cudaFuncAttributeMaxDynamicSharedMemorySize, A64_SMEM_BYTES);
        cudaFuncSetAttribute(k7b_mma, cudaFuncAttributeMaxDynamicSharedMemorySize, A128_SMEM_BYTES);
        attr_done = true;
    }

    kprep_w<<<48, 256>>>(Wh, Wog);
    k1_chunksum<<<BC, 512>>>(x);
    k3_csum_ln<<<BC, 512>>>(x, gamma, beta);
    k4_mma<<<ROWS/64, 512, A64_SMEM_BYTES>>>(x, bh);
    k5_chunkscan<<<BC, 512>>>();
    k7a_cell<<<BC, 512>>>(initcx);
    k7b_mma<<<ROWS/128, 512, A128_SMEM_BYTES>>>(x, bog, out);
}